// round 16
// baseline (speedup 1.0000x reference)
#include <cuda_runtime.h>
#include <math.h>
#include <stdint.h>

// Problem constants
#define BSZ   32
#define SSEQ  512
#define HDIM  1024
#define G3H   3072                  // 3*H
#define MROWS (BSZ * SSEQ)          // 16384
#define HB    (BSZ * HDIM)          // 32768 floats per h buffer
#define RC    147                   // recurrent CTAs (one wave on 148 SMs)

// ---------------------------------------------------------------------------
// Scratch (static device globals — no allocation at kernel_launch time)
// ---------------------------------------------------------------------------
__device__ float g_gi[(size_t)SSEQ * G3H * BSZ];     // [t][j][b]  192 MB
__device__ float g_y0[(size_t)MROWS * HDIM];         // [b][s][h]   64 MB
// ping-pong hidden state, lane-packed: (hidx,b) at ((hidx>>2)*32+b)*4+(hidx&3)
__device__ __align__(16) float g_h[2][HB];
__device__ unsigned g_rbar;                          // grid-barrier counter

// ---------------------------------------------------------------------------
// f32x2 packed-FMA helpers (FFMA2 — exact fp32)
// ---------------------------------------------------------------------------
__device__ __forceinline__ void fma2(unsigned long long& d,
                                     unsigned long long a,
                                     unsigned long long b)
{
    asm("fma.rn.f32x2 %0, %1, %2, %3;" : "=l"(d) : "l"(a), "l"(b), "l"(d));
}
__device__ __forceinline__ unsigned long long pack2(float x)
{
    unsigned long long r;
    asm("mov.b64 %0, {%1, %1};" : "=l"(r) : "f"(x));
    return r;
}
__device__ __forceinline__ float2 unpack2(unsigned long long v)
{
    float2 f;
    asm("mov.b64 {%0, %1}, %2;" : "=f"(f.x), "=f"(f.y) : "l"(v));
    return f;
}
// L1-bypassing loads (fresh data across the grid barrier)
__device__ __forceinline__ ulonglong2 ldcg_u64x2(const ulonglong2* p)
{
    ulonglong2 v;
    asm volatile("ld.global.cg.v2.u64 {%0,%1}, [%2];"
                 : "=l"(v.x), "=l"(v.y) : "l"(p));
    return v;
}
__device__ __forceinline__ float ldcg_f32(const float* p)
{
    float v;
    asm volatile("ld.global.cg.f32 %0, [%1];" : "=f"(v) : "l"(p));
    return v;
}

// ---------------------------------------------------------------------------
// GEMM (best-measured variant, R13): C[m][n] = sum_k A[m][k]*W[n][k] + bias[n]
// Double-buffered smem; B in split-half layout (LDS.128 spans 256B).
// Epilogue scatters into gi[s][n][b], m = b*512 + s.
// ---------------------------------------------------------------------------
#define BM 128
#define BN 128
#define BK 16
#define TM 8
#define TN 8

__device__ __forceinline__ int bperm(int j)
{
    return ((j & 4) << 4) + ((j >> 3) << 2) + (j & 3);
}

__global__ __launch_bounds__(256, 2)
void gemm_gi_kernel(const float* __restrict__ A,
                    const float* __restrict__ W,
                    const float* __restrict__ bias,
                    float* __restrict__ gi)
{
    __shared__ float As[2][BK][BM];
    __shared__ float Bs[2][BK][BN];

    const int tid = threadIdx.x;
    const int tx = tid & 15;
    const int ty = tid >> 4;
    const int m0 = blockIdx.y * BM;
    const int n0 = blockIdx.x * BN;

    const int lrow = tid >> 2;
    const int lc4  = (tid & 3) * 4;
    const int bp0  = bperm(lrow);
    const int bp1  = bperm(lrow + 64);

    const float* Ab = A + (size_t)(m0 + lrow) * HDIM + lc4;
    const float* Wb = W + (size_t)(n0 + lrow) * HDIM + lc4;

    float4 pa0 = *(const float4*)(Ab);
    float4 pa1 = *(const float4*)(Ab + (size_t)64 * HDIM);
    float4 pb0 = *(const float4*)(Wb);
    float4 pb1 = *(const float4*)(Wb + (size_t)64 * HDIM);

    unsigned long long acc2[TM][TN / 2];
#pragma unroll
    for (int i = 0; i < TM; i++)
#pragma unroll
        for (int j = 0; j < TN / 2; j++) acc2[i][j] = 0ull;

    {
        As[0][lc4 + 0][lrow] = pa0.x; As[0][lc4 + 1][lrow] = pa0.y;
        As[0][lc4 + 2][lrow] = pa0.z; As[0][lc4 + 3][lrow] = pa0.w;
        As[0][lc4 + 0][lrow + 64] = pa1.x; As[0][lc4 + 1][lrow + 64] = pa1.y;
        As[0][lc4 + 2][lrow + 64] = pa1.z; As[0][lc4 + 3][lrow + 64] = pa1.w;
        Bs[0][lc4 + 0][bp0] = pb0.x; Bs[0][lc4 + 1][bp0] = pb0.y;
        Bs[0][lc4 + 2][bp0] = pb0.z; Bs[0][lc4 + 3][bp0] = pb0.w;
        Bs[0][lc4 + 0][bp1] = pb1.x; Bs[0][lc4 + 1][bp1] = pb1.y;
        Bs[0][lc4 + 2][bp1] = pb1.z; Bs[0][lc4 + 3][bp1] = pb1.w;
    }
    __syncthreads();

    int buf = 0;
    for (int k0 = 0; k0 < HDIM; k0 += BK) {
        const bool nxt = (k0 + BK < HDIM);
        if (nxt) {
            pa0 = *(const float4*)(Ab + k0 + BK);
            pa1 = *(const float4*)(Ab + (size_t)64 * HDIM + k0 + BK);
            pb0 = *(const float4*)(Wb + k0 + BK);
            pb1 = *(const float4*)(Wb + (size_t)64 * HDIM + k0 + BK);
        }

#pragma unroll
        for (int kk = 0; kk < BK; kk++) {
            float4 a0 = *(const float4*)&As[buf][kk][ty * TM];
            float4 a1 = *(const float4*)&As[buf][kk][ty * TM + 4];
            ulonglong2 bl0 = *(const ulonglong2*)&Bs[buf][kk][tx * 4];
            ulonglong2 bl1 = *(const ulonglong2*)&Bs[buf][kk][64 + tx * 4];
            float ar[TM] = {a0.x, a0.y, a0.z, a0.w, a1.x, a1.y, a1.z, a1.w};
#pragma unroll
            for (int i = 0; i < TM; i++) {
                const unsigned long long aa = pack2(ar[i]);
                fma2(acc2[i][0], aa, bl0.x);
                fma2(acc2[i][1], aa, bl0.y);
                fma2(acc2[i][2], aa, bl1.x);
                fma2(acc2[i][3], aa, bl1.y);
            }
        }

        if (nxt) {
            const int nb = buf ^ 1;
            As[nb][lc4 + 0][lrow] = pa0.x; As[nb][lc4 + 1][lrow] = pa0.y;
            As[nb][lc4 + 2][lrow] = pa0.z; As[nb][lc4 + 3][lrow] = pa0.w;
            As[nb][lc4 + 0][lrow + 64] = pa1.x; As[nb][lc4 + 1][lrow + 64] = pa1.y;
            As[nb][lc4 + 2][lrow + 64] = pa1.z; As[nb][lc4 + 3][lrow + 64] = pa1.w;
            Bs[nb][lc4 + 0][bp0] = pb0.x; Bs[nb][lc4 + 1][bp0] = pb0.y;
            Bs[nb][lc4 + 2][bp0] = pb0.z; Bs[nb][lc4 + 3][bp0] = pb0.w;
            Bs[nb][lc4 + 0][bp1] = pb1.x; Bs[nb][lc4 + 1][bp1] = pb1.y;
            Bs[nb][lc4 + 2][bp1] = pb1.z; Bs[nb][lc4 + 3][bp1] = pb1.w;
            __syncthreads();
            buf = nb;
        }
    }

#pragma unroll
    for (int i = 0; i < TM; i++) {
        const int m = m0 + ty * TM + i;
        const int b = m >> 9;
        const int s = m & 511;
#pragma unroll
        for (int j2 = 0; j2 < TN / 2; j2++) {
            const float2 v = unpack2(acc2[i][j2]);
            const int n = n0 + tx * TN + 2 * j2;
            gi[((size_t)s * G3H + n) * BSZ + b]     = v.x + bias[n];
            gi[((size_t)s * G3H + n + 1) * BSZ + b] = v.y + bias[n + 1];
        }
    }
}

// ---------------------------------------------------------------------------
// Persistent GRU recurrence. 147 CTAs x 512 threads; CTA owns 7 units
// (21 gate rows, clamped dup at the tail — bit-identical writes, benign).
// W_hh slice (84 KB) resident in smem.
// Latency removals vs R15:
//  - hprev carried in a register (no per-step L2 load)
//  - gi[t+1] prefetched BEFORE the grid-barrier wait (barrier hides DRAM lat)
//  - h loads split into 2 half-k passes of 8 (halved front burst), partials
//    accumulated in sred
// ---------------------------------------------------------------------------
__global__ __launch_bounds__(512)
void gru_seq_kernel(const float* __restrict__ Whh,   // [3H, H] row-major
                    const float* __restrict__ bhh,   // [3H]
                    const float* __restrict__ gi,    // [S][3H][B]
                    float* __restrict__ hbuf,        // 2*HB ping-pong (buf0 zeroed)
                    float* __restrict__ y_out)       // [B][S][H]
{
    extern __shared__ float smem[];
    float* sw   = smem;                        // [21][1024]   84 KB
    float* sred = smem + 21 * HDIM;            // [16][21][32] 42 KB

    const int tid  = threadIdx.x;
    const int lane = tid & 31;                 // batch b
    const int w    = tid >> 5;                 // warp 0..15
    const int bx   = blockIdx.x;

    // Load this CTA's 21 W_hh rows into smem (once).
    for (int i = tid; i < 21 * (HDIM / 4); i += 512) {
        const int r  = i >> 8;
        const int c4 = (i & 255) * 4;
        const int g = r / 7, u = r - g * 7;
        int hidx = bx * 7 + u; if (hidx > HDIM - 1) hidx = HDIM - 1;
        *(float4*)&sw[(size_t)r * HDIM + c4] =
            *(const float4*)&Whh[((size_t)g * HDIM + hidx) * HDIM + c4];
    }
    __syncthreads();

    int hidx_f = bx * 7 + w; if (hidx_f > HDIM - 1) hidx_f = HDIM - 1; // valid w<7
    const int pk_f = ((hidx_f >> 2) * 32 + lane) * 4 + (hidx_f & 3);
    float bias_r = 0.f, bias_z = 0.f, bias_n = 0.f;
    float gir = 0.f, giz = 0.f, ginn = 0.f, hprev = 0.f;   // hprev: h starts at 0
    if (w < 7) {
        bias_r = bhh[hidx_f];
        bias_z = bhh[HDIM + hidx_f];
        bias_n = bhh[2 * HDIM + hidx_f];
        // gi[t=0] preload
        gir  = ldcg_f32(&gi[(size_t)hidx_f * BSZ + lane]);
        giz  = ldcg_f32(&gi[(size_t)(HDIM + hidx_f) * BSZ + lane]);
        ginn = ldcg_f32(&gi[(size_t)(2 * HDIM + hidx_f) * BSZ + lane]);
    }

    const int kq0 = w * 16;

    int cur = 0;
    for (int t = 0; t < SSEQ; ++t) {
        const float* h_in  = hbuf + (size_t)cur * HB;
        float*       h_out = hbuf + (size_t)(1 - cur) * HB;
        const ulonglong2* __restrict__ h2 = (const ulonglong2*)h_in;

        // ---- matvec in two half-k passes (burst depth 8 instead of 16) ----
#pragma unroll
        for (int half = 0; half < 2; ++half) {
            ulonglong2 hreg[8];
#pragma unroll
            for (int i = 0; i < 8; ++i)
                hreg[i] = ldcg_u64x2(&h2[(kq0 + half * 8 + i) * 32 + lane]);

            const float* wbase = sw + 4 * kq0 + half * 32;
#pragma unroll 2
            for (int rp = 0; rp < 10; ++rp) {
                const float* wp0 = wbase + (size_t)(2 * rp) * HDIM;
                const float* wp1 = wp0 + HDIM;
                unsigned long long a0 = 0ull, a1 = 0ull, b0 = 0ull, b1 = 0ull;
#pragma unroll
                for (int i = 0; i < 8; ++i) {
                    const ulonglong2 w0 = *(const ulonglong2*)(wp0 + 4 * i);
                    const ulonglong2 w1 = *(const ulonglong2*)(wp1 + 4 * i);
                    fma2(a0, w0.x, hreg[i].x);
                    fma2(a1, w0.y, hreg[i].y);
                    fma2(b0, w1.x, hreg[i].x);
                    fma2(b1, w1.y, hreg[i].y);
                }
                const float2 fa0 = unpack2(a0), fa1 = unpack2(a1);
                const float2 fb0 = unpack2(b0), fb1 = unpack2(b1);
                const float va = (fa0.x + fa0.y) + (fa1.x + fa1.y);
                const float vb = (fb0.x + fb0.y) + (fb1.x + fb1.y);
                float* s0 = &sred[((size_t)w * 21 + 2 * rp) * 32 + lane];
                float* s1 = &sred[((size_t)w * 21 + 2 * rp + 1) * 32 + lane];
                if (half == 0) { *s0 = va;  *s1 = vb; }
                else           { *s0 += va; *s1 += vb; }
            }
            {   // row 20
                const float* wp = wbase + (size_t)20 * HDIM;
                unsigned long long a0 = 0ull, a1 = 0ull;
#pragma unroll
                for (int i = 0; i < 8; ++i) {
                    const ulonglong2 w0 = *(const ulonglong2*)(wp + 4 * i);
                    fma2(a0, w0.x, hreg[i].x);
                    fma2(a1, w0.y, hreg[i].y);
                }
                const float2 fa0 = unpack2(a0), fa1 = unpack2(a1);
                const float va = (fa0.x + fa0.y) + (fa1.x + fa1.y);
                float* s0 = &sred[((size_t)w * 21 + 20) * 32 + lane];
                if (half == 0) *s0 = va; else *s0 += va;
            }
        }
        __syncthreads();

        // ---- finalize (w<7) + prefetch gi[t+1] before the barrier ----
        if (w < 7) {
            float gr = bias_r, gz = bias_z, gn = bias_n;
#pragma unroll
            for (int ww = 0; ww < 16; ++ww) {
                gr += sred[((size_t)ww * 21 + 0 * 7 + w) * 32 + lane];
                gz += sred[((size_t)ww * 21 + 1 * 7 + w) * 32 + lane];
                gn += sred[((size_t)ww * 21 + 2 * 7 + w) * 32 + lane];
            }
            const float r_ = 1.0f / (1.0f + expf(-(gir + gr)));
            const float z_ = 1.0f / (1.0f + expf(-(giz + gz)));
            const float n_ = tanhf(ginn + r_ * gn);
            const float hn = (1.0f - z_) * n_ + z_ * hprev;

            h_out[pk_f] = hn;                                   // dup CTAs: same bits
            y_out[((size_t)lane * SSEQ + t) * HDIM + hidx_f] = hn;
            hprev = hn;                                          // carried in register

            if (t + 1 < SSEQ) {                                  // hidden by barrier
                const float* gin = gi + (size_t)(t + 1) * G3H * BSZ;
                gir  = ldcg_f32(&gin[(size_t)hidx_f * BSZ + lane]);
                giz  = ldcg_f32(&gin[(size_t)(HDIM + hidx_f) * BSZ + lane]);
                ginn = ldcg_f32(&gin[(size_t)(2 * HDIM + hidx_f) * BSZ + lane]);
            }
        }
        __syncthreads();            // all stores program-ordered before arrive

        // ---- grid barrier (release/acquire on monotonic counter) ----
        if (t != SSEQ - 1) {
            if (tid == 0) {
                const unsigned tgt = (unsigned)(t + 1) * RC;
                unsigned* bar = &g_rbar;
                asm volatile("red.release.gpu.add.u32 [%0], %1;"
                             :: "l"(bar), "r"(1u) : "memory");
                unsigned v;
                do {
                    asm volatile("ld.acquire.gpu.u32 %0, [%1];"
                                 : "=r"(v) : "l"(bar) : "memory");
                } while (v < tgt);
            }
            __syncthreads();
        }
        cur ^= 1;
    }
}

// ---------------------------------------------------------------------------
__global__ void zero_h_kernel(float* __restrict__ h)
{
    const int i = blockIdx.x * 256 + threadIdx.x;
    if (i < HB) h[i] = 0.0f;
    if (i == 0) g_rbar = 0u;        // reset barrier counter (deterministic replays)
}

// h_n[0] = y0[:, S-1, :], h_n[1] = y1[:, S-1, :]
__global__ void copy_hn_kernel(const float* __restrict__ y0,
                               const float* __restrict__ y1,
                               float* __restrict__ outhn)
{
    const int i = blockIdx.x * 256 + threadIdx.x;
    if (i >= 2 * HB) return;
    const int half = HB;
    if (i < half) {
        const int b = i >> 10, h = i & 1023;
        outhn[i] = y0[((size_t)b * SSEQ + (SSEQ - 1)) * HDIM + h];
    } else {
        const int j = i - half;
        const int b = j >> 10, h = j & 1023;
        outhn[i] = y1[((size_t)b * SSEQ + (SSEQ - 1)) * HDIM + h];
    }
}

// ---------------------------------------------------------------------------
extern "C" void kernel_launch(void* const* d_in, const int* in_sizes, int n_in,
                              void* d_out, int out_size)
{
    const float* x    = (const float*)d_in[0];
    const float* Wih0 = (const float*)d_in[1];
    const float* bih0 = (const float*)d_in[2];
    const float* Whh0 = (const float*)d_in[3];
    const float* bhh0 = (const float*)d_in[4];
    const float* Wih1 = (const float*)d_in[5];
    const float* bih1 = (const float*)d_in[6];
    const float* Whh1 = (const float*)d_in[7];
    const float* bhh1 = (const float*)d_in[8];
    float* out = (float*)d_out;

    float* gi;  cudaGetSymbolAddress((void**)&gi,  g_gi);
    float* y0;  cudaGetSymbolAddress((void**)&y0,  g_y0);
    float* hb;  cudaGetSymbolAddress((void**)&hb,  g_h);

    const int SMEM_REC = (21 * HDIM + 16 * 21 * 32) * (int)sizeof(float); // 129024
    static int smem_set = 0;
    if (!smem_set) {
        cudaFuncSetAttribute(gru_seq_kernel,
                             cudaFuncAttributeMaxDynamicSharedMemorySize, SMEM_REC);
        smem_set = 1;
    }

    const dim3 gemm_grid(G3H / BN, MROWS / BM);   // (24, 128)

    // ---- Layer 0 ----
    gemm_gi_kernel<<<gemm_grid, 256>>>(x, Wih0, bih0, gi);
    zero_h_kernel<<<(HB + 255) / 256, 256>>>(hb);
    gru_seq_kernel<<<RC, 512, SMEM_REC>>>(Whh0, bhh0, gi, hb, y0);

    // ---- Layer 1 ----
    gemm_gi_kernel<<<gemm_grid, 256>>>(y0, Wih1, bih1, gi);
    zero_h_kernel<<<(HB + 255) / 256, 256>>>(hb);
    gru_seq_kernel<<<RC, 512, SMEM_REC>>>(Whh1, bhh1, gi, hb, out);

    // ---- h_n tail (only if the harness output includes it) ----
    const long long need = (long long)MROWS * HDIM + 2LL * HB;
    if ((long long)out_size >= need) {
        copy_hn_kernel<<<(2 * HB + 255) / 256, 256>>>(y0, out, out + (size_t)MROWS * HDIM);
    }
}

// round 17
// speedup vs baseline: 1.5718x; 1.5718x over previous
#include <cuda_runtime.h>
#include <math.h>
#include <stdint.h>

// Problem constants
#define BSZ   32
#define SSEQ  512
#define HDIM  1024
#define G3H   3072                  // 3*H
#define MROWS (BSZ * SSEQ)          // 16384
#define HB    (BSZ * HDIM)          // 32768 floats per h buffer
#define RC    147                   // recurrent CTAs (one wave on 148 SMs)

// ---------------------------------------------------------------------------
// Scratch (static device globals — no allocation at kernel_launch time)
// ---------------------------------------------------------------------------
__device__ float g_gi[(size_t)SSEQ * G3H * BSZ];     // [t][j][b]  192 MB
__device__ float g_y0[(size_t)MROWS * HDIM];         // [b][s][h]   64 MB
// ping-pong hidden state, lane-packed: (hidx,b) at ((hidx>>2)*32+b)*4+(hidx&3)
__device__ __align__(16) float g_h[2][HB];
__device__ unsigned g_rbar;                          // grid-barrier counter

// ---------------------------------------------------------------------------
// f32x2 packed-FMA helpers (FFMA2 — exact fp32)
// ---------------------------------------------------------------------------
__device__ __forceinline__ void fma2(unsigned long long& d,
                                     unsigned long long a,
                                     unsigned long long b)
{
    asm("fma.rn.f32x2 %0, %1, %2, %3;" : "=l"(d) : "l"(a), "l"(b), "l"(d));
}
__device__ __forceinline__ unsigned long long pack2(float x)
{
    unsigned long long r;
    asm("mov.b64 %0, {%1, %1};" : "=l"(r) : "f"(x));
    return r;
}
__device__ __forceinline__ float2 unpack2(unsigned long long v)
{
    float2 f;
    asm("mov.b64 {%0, %1}, %2;" : "=f"(f.x), "=f"(f.y) : "l"(v));
    return f;
}
// L1-bypassing loads (fresh data across the grid barrier)
__device__ __forceinline__ ulonglong2 ldcg_u64x2(const ulonglong2* p)
{
    ulonglong2 v;
    asm volatile("ld.global.cg.v2.u64 {%0,%1}, [%2];"
                 : "=l"(v.x), "=l"(v.y) : "l"(p));
    return v;
}
__device__ __forceinline__ float ldcg_f32(const float* p)
{
    float v;
    asm volatile("ld.global.cg.f32 %0, [%1];" : "=f"(v) : "l"(p));
    return v;
}

// ---------------------------------------------------------------------------
// GEMM (best-measured variant, R13): C[m][n] = sum_k A[m][k]*W[n][k] + bias[n]
// Double-buffered smem; B in split-half layout (LDS.128 spans 256B).
// Epilogue scatters into gi[s][n][b], m = b*512 + s.
// ---------------------------------------------------------------------------
#define BM 128
#define BN 128
#define BK 16
#define TM 8
#define TN 8

__device__ __forceinline__ int bperm(int j)
{
    return ((j & 4) << 4) + ((j >> 3) << 2) + (j & 3);
}

__global__ __launch_bounds__(256, 2)
void gemm_gi_kernel(const float* __restrict__ A,
                    const float* __restrict__ W,
                    const float* __restrict__ bias,
                    float* __restrict__ gi)
{
    __shared__ float As[2][BK][BM];
    __shared__ float Bs[2][BK][BN];

    const int tid = threadIdx.x;
    const int tx = tid & 15;
    const int ty = tid >> 4;
    const int m0 = blockIdx.y * BM;
    const int n0 = blockIdx.x * BN;

    const int lrow = tid >> 2;
    const int lc4  = (tid & 3) * 4;
    const int bp0  = bperm(lrow);
    const int bp1  = bperm(lrow + 64);

    const float* Ab = A + (size_t)(m0 + lrow) * HDIM + lc4;
    const float* Wb = W + (size_t)(n0 + lrow) * HDIM + lc4;

    float4 pa0 = *(const float4*)(Ab);
    float4 pa1 = *(const float4*)(Ab + (size_t)64 * HDIM);
    float4 pb0 = *(const float4*)(Wb);
    float4 pb1 = *(const float4*)(Wb + (size_t)64 * HDIM);

    unsigned long long acc2[TM][TN / 2];
#pragma unroll
    for (int i = 0; i < TM; i++)
#pragma unroll
        for (int j = 0; j < TN / 2; j++) acc2[i][j] = 0ull;

    {
        As[0][lc4 + 0][lrow] = pa0.x; As[0][lc4 + 1][lrow] = pa0.y;
        As[0][lc4 + 2][lrow] = pa0.z; As[0][lc4 + 3][lrow] = pa0.w;
        As[0][lc4 + 0][lrow + 64] = pa1.x; As[0][lc4 + 1][lrow + 64] = pa1.y;
        As[0][lc4 + 2][lrow + 64] = pa1.z; As[0][lc4 + 3][lrow + 64] = pa1.w;
        Bs[0][lc4 + 0][bp0] = pb0.x; Bs[0][lc4 + 1][bp0] = pb0.y;
        Bs[0][lc4 + 2][bp0] = pb0.z; Bs[0][lc4 + 3][bp0] = pb0.w;
        Bs[0][lc4 + 0][bp1] = pb1.x; Bs[0][lc4 + 1][bp1] = pb1.y;
        Bs[0][lc4 + 2][bp1] = pb1.z; Bs[0][lc4 + 3][bp1] = pb1.w;
    }
    __syncthreads();

    int buf = 0;
    for (int k0 = 0; k0 < HDIM; k0 += BK) {
        const bool nxt = (k0 + BK < HDIM);
        if (nxt) {
            pa0 = *(const float4*)(Ab + k0 + BK);
            pa1 = *(const float4*)(Ab + (size_t)64 * HDIM + k0 + BK);
            pb0 = *(const float4*)(Wb + k0 + BK);
            pb1 = *(const float4*)(Wb + (size_t)64 * HDIM + k0 + BK);
        }

#pragma unroll
        for (int kk = 0; kk < BK; kk++) {
            float4 a0 = *(const float4*)&As[buf][kk][ty * TM];
            float4 a1 = *(const float4*)&As[buf][kk][ty * TM + 4];
            ulonglong2 bl0 = *(const ulonglong2*)&Bs[buf][kk][tx * 4];
            ulonglong2 bl1 = *(const ulonglong2*)&Bs[buf][kk][64 + tx * 4];
            float ar[TM] = {a0.x, a0.y, a0.z, a0.w, a1.x, a1.y, a1.z, a1.w};
#pragma unroll
            for (int i = 0; i < TM; i++) {
                const unsigned long long aa = pack2(ar[i]);
                fma2(acc2[i][0], aa, bl0.x);
                fma2(acc2[i][1], aa, bl0.y);
                fma2(acc2[i][2], aa, bl1.x);
                fma2(acc2[i][3], aa, bl1.y);
            }
        }

        if (nxt) {
            const int nb = buf ^ 1;
            As[nb][lc4 + 0][lrow] = pa0.x; As[nb][lc4 + 1][lrow] = pa0.y;
            As[nb][lc4 + 2][lrow] = pa0.z; As[nb][lc4 + 3][lrow] = pa0.w;
            As[nb][lc4 + 0][lrow + 64] = pa1.x; As[nb][lc4 + 1][lrow + 64] = pa1.y;
            As[nb][lc4 + 2][lrow + 64] = pa1.z; As[nb][lc4 + 3][lrow + 64] = pa1.w;
            Bs[nb][lc4 + 0][bp0] = pb0.x; Bs[nb][lc4 + 1][bp0] = pb0.y;
            Bs[nb][lc4 + 2][bp0] = pb0.z; Bs[nb][lc4 + 3][bp0] = pb0.w;
            Bs[nb][lc4 + 0][bp1] = pb1.x; Bs[nb][lc4 + 1][bp1] = pb1.y;
            Bs[nb][lc4 + 2][bp1] = pb1.z; Bs[nb][lc4 + 3][bp1] = pb1.w;
            __syncthreads();
            buf = nb;
        }
    }

#pragma unroll
    for (int i = 0; i < TM; i++) {
        const int m = m0 + ty * TM + i;
        const int b = m >> 9;
        const int s = m & 511;
#pragma unroll
        for (int j2 = 0; j2 < TN / 2; j2++) {
            const float2 v = unpack2(acc2[i][j2]);
            const int n = n0 + tx * TN + 2 * j2;
            gi[((size_t)s * G3H + n) * BSZ + b]     = v.x + bias[n];
            gi[((size_t)s * G3H + n + 1) * BSZ + b] = v.y + bias[n + 1];
        }
    }
}

// ---------------------------------------------------------------------------
// Persistent GRU recurrence (R15 structure + two safe latency removals).
// 147 CTAs x 512 threads; CTA owns 7 units (21 gate rows; clamped dup at the
// tail — bit-identical duplicate writes, benign). W_hh slice in smem.
//  - single 16-deep register h-load pass (R15 best)
//  - hprev carried in a register (no per-step L2 load)
//  - gi[t+1] prefetched BEFORE the grid-barrier wait (barrier hides DRAM lat)
//  - barrier poll WITH __nanosleep backoff (R16 lesson: hot spin throttles L2)
// ---------------------------------------------------------------------------
__global__ __launch_bounds__(512)
void gru_seq_kernel(const float* __restrict__ Whh,   // [3H, H] row-major
                    const float* __restrict__ bhh,   // [3H]
                    const float* __restrict__ gi,    // [S][3H][B]
                    float* __restrict__ hbuf,        // 2*HB ping-pong (buf0 zeroed)
                    float* __restrict__ y_out)       // [B][S][H]
{
    extern __shared__ float smem[];
    float* sw   = smem;                        // [21][1024]   84 KB
    float* sred = smem + 21 * HDIM;            // [16][21][32] 42 KB

    const int tid  = threadIdx.x;
    const int lane = tid & 31;                 // batch b
    const int w    = tid >> 5;                 // warp 0..15
    const int bx   = blockIdx.x;

    // Load this CTA's 21 W_hh rows into smem (once).
    for (int i = tid; i < 21 * (HDIM / 4); i += 512) {
        const int r  = i >> 8;
        const int c4 = (i & 255) * 4;
        const int g = r / 7, u = r - g * 7;
        int hidx = bx * 7 + u; if (hidx > HDIM - 1) hidx = HDIM - 1;
        *(float4*)&sw[(size_t)r * HDIM + c4] =
            *(const float4*)&Whh[((size_t)g * HDIM + hidx) * HDIM + c4];
    }
    __syncthreads();

    int hidx_f = bx * 7 + w; if (hidx_f > HDIM - 1) hidx_f = HDIM - 1; // valid w<7
    const int pk_f = ((hidx_f >> 2) * 32 + lane) * 4 + (hidx_f & 3);
    float bias_r = 0.f, bias_z = 0.f, bias_n = 0.f;
    float gir = 0.f, giz = 0.f, ginn = 0.f, hprev = 0.f;   // h starts at 0
    if (w < 7) {
        bias_r = bhh[hidx_f];
        bias_z = bhh[HDIM + hidx_f];
        bias_n = bhh[2 * HDIM + hidx_f];
        // gi[t=0] preload
        gir  = ldcg_f32(&gi[(size_t)hidx_f * BSZ + lane]);
        giz  = ldcg_f32(&gi[(size_t)(HDIM + hidx_f) * BSZ + lane]);
        ginn = ldcg_f32(&gi[(size_t)(2 * HDIM + hidx_f) * BSZ + lane]);
    }

    const int kq0 = w * 16;

    int cur = 0;
    for (int t = 0; t < SSEQ; ++t) {
        const float* h_in  = hbuf + (size_t)cur * HB;
        float*       h_out = hbuf + (size_t)(1 - cur) * HB;
        const ulonglong2* __restrict__ h2 = (const ulonglong2*)h_in;

        // --- load warp's h chunk (64 floats) into registers, L1-bypassing ---
        ulonglong2 hreg[16];
#pragma unroll
        for (int i = 0; i < 16; ++i)
            hreg[i] = ldcg_u64x2(&h2[(kq0 + i) * 32 + lane]);

        // --- 10 row-pairs + 1 single row; 4 (2) live accumulator chains ---
        const float* wbase = sw + 4 * kq0;
#pragma unroll 2
        for (int rp = 0; rp < 10; ++rp) {
            const float* wp0 = wbase + (size_t)(2 * rp) * HDIM;
            const float* wp1 = wp0 + HDIM;
            unsigned long long a0 = 0ull, a1 = 0ull, b0 = 0ull, b1 = 0ull;
#pragma unroll
            for (int i = 0; i < 16; ++i) {
                const ulonglong2 w0 = *(const ulonglong2*)(wp0 + 4 * i);
                const ulonglong2 w1 = *(const ulonglong2*)(wp1 + 4 * i);
                fma2(a0, w0.x, hreg[i].x);
                fma2(a1, w0.y, hreg[i].y);
                fma2(b0, w1.x, hreg[i].x);
                fma2(b1, w1.y, hreg[i].y);
            }
            const float2 fa0 = unpack2(a0), fa1 = unpack2(a1);
            const float2 fb0 = unpack2(b0), fb1 = unpack2(b1);
            sred[((size_t)w * 21 + 2 * rp) * 32 + lane]     = (fa0.x + fa0.y) + (fa1.x + fa1.y);
            sred[((size_t)w * 21 + 2 * rp + 1) * 32 + lane] = (fb0.x + fb0.y) + (fb1.x + fb1.y);
        }
        {   // row 20
            const float* wp = wbase + (size_t)20 * HDIM;
            unsigned long long a0 = 0ull, a1 = 0ull;
#pragma unroll
            for (int i = 0; i < 16; ++i) {
                const ulonglong2 w0 = *(const ulonglong2*)(wp + 4 * i);
                fma2(a0, w0.x, hreg[i].x);
                fma2(a1, w0.y, hreg[i].y);
            }
            const float2 fa0 = unpack2(a0), fa1 = unpack2(a1);
            sred[((size_t)w * 21 + 20) * 32 + lane] = (fa0.x + fa0.y) + (fa1.x + fa1.y);
        }
        __syncthreads();

        // ---- finalize (w<7) + prefetch gi[t+1] before the barrier ----
        if (w < 7) {
            float gr = bias_r, gz = bias_z, gn = bias_n;
#pragma unroll
            for (int ww = 0; ww < 16; ++ww) {
                gr += sred[((size_t)ww * 21 + 0 * 7 + w) * 32 + lane];
                gz += sred[((size_t)ww * 21 + 1 * 7 + w) * 32 + lane];
                gn += sred[((size_t)ww * 21 + 2 * 7 + w) * 32 + lane];
            }
            const float r_ = 1.0f / (1.0f + expf(-(gir + gr)));
            const float z_ = 1.0f / (1.0f + expf(-(giz + gz)));
            const float n_ = tanhf(ginn + r_ * gn);
            const float hn = (1.0f - z_) * n_ + z_ * hprev;

            h_out[pk_f] = hn;                                   // dup CTAs: same bits
            y_out[((size_t)lane * SSEQ + t) * HDIM + hidx_f] = hn;
            hprev = hn;                                          // carried in register

            if (t + 1 < SSEQ) {                                  // hidden by barrier
                const float* gin = gi + (size_t)(t + 1) * G3H * BSZ;
                gir  = ldcg_f32(&gin[(size_t)hidx_f * BSZ + lane]);
                giz  = ldcg_f32(&gin[(size_t)(HDIM + hidx_f) * BSZ + lane]);
                ginn = ldcg_f32(&gin[(size_t)(2 * HDIM + hidx_f) * BSZ + lane]);
            }
        }
        __syncthreads();            // all stores program-ordered before arrive

        // ---- grid barrier (release/acquire + nanosleep backoff) ----
        if (t != SSEQ - 1) {
            if (tid == 0) {
                const unsigned tgt = (unsigned)(t + 1) * RC;
                unsigned* bar = &g_rbar;
                asm volatile("red.release.gpu.add.u32 [%0], %1;"
                             :: "l"(bar), "r"(1u) : "memory");
                unsigned v;
                for (;;) {
                    asm volatile("ld.acquire.gpu.u32 %0, [%1];"
                                 : "=r"(v) : "l"(bar) : "memory");
                    if (v >= tgt) break;
                    __nanosleep(32);
                }
            }
            __syncthreads();
        }
        cur ^= 1;
    }
}

// ---------------------------------------------------------------------------
__global__ void zero_h_kernel(float* __restrict__ h)
{
    const int i = blockIdx.x * 256 + threadIdx.x;
    if (i < HB) h[i] = 0.0f;
    if (i == 0) g_rbar = 0u;        // reset barrier counter (deterministic replays)
}

// h_n[0] = y0[:, S-1, :], h_n[1] = y1[:, S-1, :]
__global__ void copy_hn_kernel(const float* __restrict__ y0,
                               const float* __restrict__ y1,
                               float* __restrict__ outhn)
{
    const int i = blockIdx.x * 256 + threadIdx.x;
    if (i >= 2 * HB) return;
    const int half = HB;
    if (i < half) {
        const int b = i >> 10, h = i & 1023;
        outhn[i] = y0[((size_t)b * SSEQ + (SSEQ - 1)) * HDIM + h];
    } else {
        const int j = i - half;
        const int b = j >> 10, h = j & 1023;
        outhn[i] = y1[((size_t)b * SSEQ + (SSEQ - 1)) * HDIM + h];
    }
}

// ---------------------------------------------------------------------------
extern "C" void kernel_launch(void* const* d_in, const int* in_sizes, int n_in,
                              void* d_out, int out_size)
{
    const float* x    = (const float*)d_in[0];
    const float* Wih0 = (const float*)d_in[1];
    const float* bih0 = (const float*)d_in[2];
    const float* Whh0 = (const float*)d_in[3];
    const float* bhh0 = (const float*)d_in[4];
    const float* Wih1 = (const float*)d_in[5];
    const float* bih1 = (const float*)d_in[6];
    const float* Whh1 = (const float*)d_in[7];
    const float* bhh1 = (const float*)d_in[8];
    float* out = (float*)d_out;

    float* gi;  cudaGetSymbolAddress((void**)&gi,  g_gi);
    float* y0;  cudaGetSymbolAddress((void**)&y0,  g_y0);
    float* hb;  cudaGetSymbolAddress((void**)&hb,  g_h);

    const int SMEM_REC = (21 * HDIM + 16 * 21 * 32) * (int)sizeof(float); // 129024
    static int smem_set = 0;
    if (!smem_set) {
        cudaFuncSetAttribute(gru_seq_kernel,
                             cudaFuncAttributeMaxDynamicSharedMemorySize, SMEM_REC);
        smem_set = 1;
    }

    const dim3 gemm_grid(G3H / BN, MROWS / BM);   // (24, 128)

    // ---- Layer 0 ----
    gemm_gi_kernel<<<gemm_grid, 256>>>(x, Wih0, bih0, gi);
    zero_h_kernel<<<(HB + 255) / 256, 256>>>(hb);
    gru_seq_kernel<<<RC, 512, SMEM_REC>>>(Whh0, bhh0, gi, hb, y0);

    // ---- Layer 1 ----
    gemm_gi_kernel<<<gemm_grid, 256>>>(y0, Wih1, bih1, gi);
    zero_h_kernel<<<(HB + 255) / 256, 256>>>(hb);
    gru_seq_kernel<<<RC, 512, SMEM_REC>>>(Whh1, bhh1, gi, hb, out);

    // ---- h_n tail (only if the harness output includes it) ----
    const long long need = (long long)MROWS * HDIM + 2LL * HB;
    if ((long long)out_size >= need) {
        copy_hn_kernel<<<(2 * HB + 255) / 256, 256>>>(y0, out, out + (size_t)MROWS * HDIM);
    }
}